// round 11
// baseline (speedup 1.0000x reference)
#include <cuda_runtime.h>
#include <cuda_bf16.h>
#include <cstdint>

// ---------------- problem constants ----------------
#define BROWS 16384
#define DIN   512
#define NSP   26
#define EMB   128
#define OUTD  512
#define NI    27
#define NTRI  378
// packed-A layout (bf16): [0..511]=hi(dense) [512..889]=hi(ztri) [890..895]=0
//                         [896..1407]=lo(dense) [1408..1785]=lo(ztri) [1786..1791]=0
#define KAP   1792
#define ALO   896
#define KWO   2688          // Wo pack: [hi(896) | lo(896) | hi(896)]
#define KWP   1536          // Wp pack: [hi(512) | lo(512) | hi(512)]

// ---------------- device scratch (ONLY referenced from device code!) --------
__device__ __align__(16) __nv_bfloat16 g_apack[BROWS * KAP];
__device__ __align__(16) __nv_bfloat16 g_wopack[OUTD * KWO];
__device__ __align__(16) __nv_bfloat16 g_wppack[EMB * KWP];
__device__ __align__(16) float         g_proj[BROWS * EMB];

// ---------------- helpers ----------------
__device__ __forceinline__ void bf_split(float v, __nv_bfloat16& h, __nv_bfloat16& l) {
    h = __float2bfloat16(v);
    l = __float2bfloat16(v - __bfloat162float(h));
}
__device__ __forceinline__ uint32_t smem_u32(const void* p) {
    uint32_t a;
    asm("{ .reg .u64 t; cvta.to.shared.u64 t, %1; cvt.u32.u64 %0, t; }" : "=r"(a) : "l"(p));
    return a;
}
__device__ __forceinline__ void cp_async16(uint32_t s, const void* g) {
    asm volatile("cp.async.cg.shared.global [%0], [%1], 16;" :: "r"(s), "l"(g) : "memory");
}
__device__ __forceinline__ void ldsm_x4(uint32_t& r0, uint32_t& r1, uint32_t& r2, uint32_t& r3,
                                        uint32_t addr) {
    asm volatile("ldmatrix.sync.aligned.m8n8.x4.shared.b16 {%0,%1,%2,%3}, [%4];"
                 : "=r"(r0), "=r"(r1), "=r"(r2), "=r"(r3) : "r"(addr));
}
__device__ __forceinline__ void mma16816(float* c,
                                         uint32_t a0, uint32_t a1, uint32_t a2, uint32_t a3,
                                         uint32_t b0, uint32_t b1) {
    asm volatile("mma.sync.aligned.m16n8k16.row.col.f32.bf16.bf16.f32 "
                 "{%0,%1,%2,%3}, {%4,%5,%6,%7}, {%8,%9}, {%0,%1,%2,%3};"
                 : "+f"(c[0]), "+f"(c[1]), "+f"(c[2]), "+f"(c[3])
                 : "r"(a0), "r"(a1), "r"(a2), "r"(a3), "r"(b0), "r"(b1));
}

// ---------------------------------------------------------------------------
// pack kernels
// ---------------------------------------------------------------------------
__global__ void pack_dense_kernel(const float* __restrict__ dense) {
    size_t t   = (size_t)blockIdx.x * 256 + threadIdx.x;   // one float4 each
    size_t row = t >> 7;
    int    c4  = (int)(t & 127) * 4;
    float4 v   = *(const float4*)(dense + row * DIN + c4);
    float  vv[4] = {v.x, v.y, v.z, v.w};
    __nv_bfloat16 h[4], l[4];
#pragma unroll
    for (int i = 0; i < 4; i++) bf_split(vv[i], h[i], l[i]);
    __nv_bfloat16* a = g_apack + row * KAP;
    *(__nv_bfloat162*)(a + c4)           = __nv_bfloat162(h[0], h[1]);
    *(__nv_bfloat162*)(a + c4 + 2)       = __nv_bfloat162(h[2], h[3]);
    *(__nv_bfloat162*)(a + ALO + c4)     = __nv_bfloat162(l[0], l[1]);
    *(__nv_bfloat162*)(a + ALO + c4 + 2) = __nv_bfloat162(l[2], l[3]);
}

__global__ void pack_wo_kernel(const float* __restrict__ Wo) {
    int n = blockIdx.x;
    for (int k = threadIdx.x; k < 896; k += 256) {
        float v = (k < 890) ? Wo[(size_t)n * 890 + k] : 0.0f;
        __nv_bfloat16 h, l;
        bf_split(v, h, l);
        __nv_bfloat16* w = g_wopack + (size_t)n * KWO;
        w[k] = h; w[896 + k] = l; w[1792 + k] = h;
    }
}

__global__ void pack_wp_kernel(const float* __restrict__ Wp) {
    int n = blockIdx.x;
    for (int k = threadIdx.x; k < 512; k += 256) {
        float v = Wp[(size_t)n * 512 + k];
        __nv_bfloat16 h, l;
        bf_split(v, h, l);
        __nv_bfloat16* w = g_wppack + (size_t)n * KWP;
        w[k] = h; w[512 + k] = l; w[1024 + k] = h;
    }
}

// ---------------------------------------------------------------------------
// HMMA (mma.sync bf16) tiled GEMM with 3-segment split-K remap.
// MODE 0: proj  -> A=g_apack(K=KAP), W=g_wppack(K=KWP), C=g_proj (ldc=EMB)
// MODE 1: out   -> A=g_apack(K=KAP), W=g_wopack(K=KWO), C=arg    (ldc=OUTD)
// 256 threads = 8 warps, warp tile 64x32 via m16n8k16; BK=32 chunks.
// chunk c: A cols ((c/SC)<2 ? 0 : ALO) + (c%SC)*32, W cols c*32.
// 3-stage cp.async ring (prefetch depth 2), ONE __syncthreads per chunk.
// ---------------------------------------------------------------------------
#define PADK   40                      // bf16 row stride -> 80B, conflict-free
#define STAGEB (128 * PADK)            // bf16 elements per stage per matrix
#define SMEM_BYTES (3 * 2 * STAGEB * 2)  // 3 stages x (A+B) x 2B = 61440

template<int NCH, int SC, int MODE>
__global__ void __launch_bounds__(256, 2)
gemm_mma_kernel(const float* __restrict__ bias, float* __restrict__ C_arg)
{
    extern __shared__ __align__(16) __nv_bfloat16 smem[];
    // layout: [A0 B0 A1 B1 A2 B2], each STAGEB bf16
    __nv_bfloat16* As[3] = { smem,              smem + 2 * STAGEB, smem + 4 * STAGEB };
    __nv_bfloat16* Bs[3] = { smem + STAGEB,     smem + 3 * STAGEB, smem + 5 * STAGEB };

    const __nv_bfloat16* __restrict__ A = g_apack;
    const __nv_bfloat16* __restrict__ W = (MODE == 0) ? g_wppack : g_wopack;
    const int KA  = KAP;
    const int KW  = (MODE == 0) ? KWP : KWO;
    float* __restrict__ C = (MODE == 0) ? g_proj : C_arg;
    const int ldc = (MODE == 0) ? EMB : OUTD;

    const int tid  = threadIdx.x;
    const int wid  = tid >> 5;
    const int lane = tid & 31;
    const int wm   = wid >> 2;     // 0..1 warp-row (64 rows each)
    const int wn   = wid & 3;      // 0..3 warp-col (32 cols each)
    const int m0   = blockIdx.y * 128;
    const int n0   = blockIdx.x * 128;

    float acc[4][4][4];
#pragma unroll
    for (int i = 0; i < 4; i++)
#pragma unroll
        for (int j = 0; j < 4; j++)
#pragma unroll
            for (int q = 0; q < 4; q++) acc[i][j][q] = 0.0f;

    auto load = [&](int c, int buf) {
        int seg = c / SC, r = c - seg * SC;
        int ka0 = ((seg < 2) ? 0 : ALO) + r * 32;
        int kw0 = c * 32;
#pragma unroll
        for (int i = 0; i < 2; i++) {
            int idx = tid + i * 256;           // 512 uint4 tasks each for A and B
            int row = idx >> 2, j = idx & 3;
            cp_async16(smem_u32(&As[buf][row * PADK + j * 8]),
                       A + (size_t)(m0 + row) * KA + ka0 + j * 8);
            cp_async16(smem_u32(&Bs[buf][row * PADK + j * 8]),
                       W + (size_t)(n0 + row) * KW + kw0 + j * 8);
        }
        asm volatile("cp.async.commit_group;" ::: "memory");
    };

    auto compute = [&](int buf) {
#pragma unroll
        for (int ks = 0; ks < 2; ks++) {
            uint32_t a[4][4], b[2][4];
#pragma unroll
            for (int mt = 0; mt < 4; mt++) {
                uint32_t addr = smem_u32(
                    &As[buf][(wm * 64 + mt * 16 + (lane & 15)) * PADK +
                             ks * 16 + (lane >> 4) * 8]);
                ldsm_x4(a[mt][0], a[mt][1], a[mt][2], a[mt][3], addr);
            }
#pragma unroll
            for (int nt2 = 0; nt2 < 2; nt2++) {
                uint32_t addr = smem_u32(
                    &Bs[buf][(wn * 32 + nt2 * 16 + ((lane >> 4) & 1) * 8 + (lane & 7)) * PADK +
                             ks * 16 + ((lane >> 3) & 1) * 8]);
                ldsm_x4(b[nt2][0], b[nt2][1], b[nt2][2], b[nt2][3], addr);
            }
#pragma unroll
            for (int mt = 0; mt < 4; mt++)
#pragma unroll
                for (int nt = 0; nt < 4; nt++) {
                    int nt2 = nt >> 1, hb = (nt & 1) * 2;
                    mma16816(acc[mt][nt],
                             a[mt][0], a[mt][1], a[mt][2], a[mt][3],
                             b[nt2][hb], b[nt2][hb + 1]);
                }
        }
    };

    // prologue: prefetch depth 2
    load(0, 0);
    load(1, 1);

#pragma unroll 1
    for (int c = 0; c < NCH; c++) {
        if (c + 1 < NCH) {
            asm volatile("cp.async.wait_group 1;" ::: "memory");  // group c done
        } else {
            asm volatile("cp.async.wait_group 0;" ::: "memory");
        }
        __syncthreads();   // data visible to all warps; also fences buf reuse:
                           // compute(c-1) on buf (c-1)%3 == (c+2)%3 is pre-sync
        if (c + 2 < NCH) load(c + 2, (c + 2) % 3);
        compute(c % 3);
    }

    // epilogue
    const int r4 = lane >> 2;
    const int c2 = (lane & 3) * 2;
#pragma unroll
    for (int mt = 0; mt < 4; mt++) {
        int mrow = m0 + wm * 64 + mt * 16 + r4;
#pragma unroll
        for (int nt = 0; nt < 4; nt++) {
            int ncol = n0 + wn * 32 + nt * 8 + c2;
            float2 bv = *(const float2*)&bias[ncol];
            float2 o0, o1;
            o0.x = acc[mt][nt][0] + bv.x; o0.y = acc[mt][nt][1] + bv.y;
            o1.x = acc[mt][nt][2] + bv.x; o1.y = acc[mt][nt][3] + bv.y;
            *(float2*)&C[(size_t)mrow * ldc + ncol]       = o0;
            *(float2*)&C[(size_t)(mrow + 8) * ldc + ncol] = o1;
        }
    }
}

// ---------------------------------------------------------------------------
// zflat: per-row Z = T T^T lower-tri, T = [proj_row; sparse_row] (27x128).
// Writes bf16 hi/lo into A_pack cols [512..889]/[1408..1785]; zeroes pads.
// ---------------------------------------------------------------------------
__global__ void __launch_bounds__(64)
zflat_kernel(const float* __restrict__ sparse)
{
    __shared__ __align__(16) float Tt[2][128 * 28];

    const int w    = threadIdx.x >> 5;
    const int lane = threadIdx.x & 31;
    const size_t b = (size_t)blockIdx.x * 2 + w;
    float* T = Tt[w];
    __nv_bfloat16* arow = g_apack + b * KAP;

    if (lane < 6) {
        arow[890 + lane]       = __float2bfloat16(0.0f);
        arow[ALO + 890 + lane] = __float2bfloat16(0.0f);
    }

    {
        const float* src = g_proj + b * 128;
#pragma unroll
        for (int c = 0; c < 4; c++) { int e = lane + 32 * c; T[e * 28 + 0] = src[e]; }
    }
    for (int i = 1; i < NI; i++) {
        const float* src = sparse + (b * NSP + (i - 1)) * 128;
#pragma unroll
        for (int c = 0; c < 4; c++) { int e = lane + 32 * c; T[e * 28 + i] = src[e]; }
    }
    __syncwarp();

    if (lane < 28) {
        int ti = 0, rem = lane;
        while (rem > ti) { rem -= (ti + 1); ti++; }
        int tj = rem;

        float acc[4][4];
#pragma unroll
        for (int r = 0; r < 4; r++)
#pragma unroll
            for (int c = 0; c < 4; c++) acc[r][c] = 0.0f;

#pragma unroll 4
        for (int e = 0; e < 128; e++) {
            float4 av = *(const float4*)&T[e * 28 + 4 * ti];
            float4 bv = *(const float4*)&T[e * 28 + 4 * tj];
            float a[4]  = {av.x, av.y, av.z, av.w};
            float c4[4] = {bv.x, bv.y, bv.z, bv.w};
#pragma unroll
            for (int r = 0; r < 4; r++)
#pragma unroll
                for (int c = 0; c < 4; c++) acc[r][c] += a[r] * c4[c];
        }

#pragma unroll
        for (int r = 0; r < 4; r++) {
            int i = 4 * ti + r;
            if (i < NI) {
#pragma unroll
                for (int c = 0; c < 4; c++) {
                    int j = 4 * tj + c;
                    if (j <= i) {
                        int idx = i * (i + 1) / 2 + j;
                        __nv_bfloat16 h, l;
                        bf_split(acc[r][c], h, l);
                        arow[512 + idx]       = h;
                        arow[ALO + 512 + idx] = l;
                    }
                }
            }
        }
    }
}

// ---------------------------------------------------------------------------
// launch — __device__ globals never referenced from host code (MODE binding).
// ---------------------------------------------------------------------------
extern "C" void kernel_launch(void* const* d_in, const int* in_sizes, int n_in,
                              void* d_out, int out_size) {
    const float* dense  = (const float*)d_in[0];   // [16384, 512]
    const float* sparse = (const float*)d_in[1];   // [16384, 26, 128]
    const float* Wp     = (const float*)d_in[2];   // [128, 512]
    const float* bp     = (const float*)d_in[3];   // [128]
    const float* Wo     = (const float*)d_in[4];   // [512, 890]
    const float* bo     = (const float*)d_in[5];   // [512]
    float* out = (float*)d_out;                    // [16384, 512]

    cudaFuncSetAttribute(gemm_mma_kernel<48, 16, 0>,
                         cudaFuncAttributeMaxDynamicSharedMemorySize, SMEM_BYTES);
    cudaFuncSetAttribute(gemm_mma_kernel<84, 28, 1>,
                         cudaFuncAttributeMaxDynamicSharedMemorySize, SMEM_BYTES);

    pack_dense_kernel<<<BROWS * DIN / (4 * 256), 256>>>(dense);
    pack_wp_kernel<<<EMB, 256>>>(Wp);
    pack_wo_kernel<<<OUTD, 256>>>(Wo);

    // proj: g_proj[B,128] = dense @ Wp^T + bp   (K = 3x512 split -> 48 chunks)
    gemm_mma_kernel<48, 16, 0><<<dim3(1, BROWS / 128), 256, SMEM_BYTES>>>(bp, nullptr);

    zflat_kernel<<<BROWS / 2, 64>>>(sparse);

    // out: [B,512] = [dense|Ztri] @ Wo^T + bo   (K = 3x896 split -> 84 chunks)
    gemm_mma_kernel<84, 28, 1><<<dim3(OUTD / 128, BROWS / 128), 256, SMEM_BYTES>>>(bo, out);
}